// round 14
// baseline (speedup 1.0000x reference)
#include <cuda_runtime.h>
#include <cuda_bf16.h>
#include <cstdint>

// Problem constants
#define Bv   32
#define Nv   128
#define Fv   78
#define Hv   256
#define Sv   20
#define Tv   13
#define Lv   3
#define ALPHA 0.2f
#define NEG_INF -9000000000000000.0f

#define BN (Bv*Nv)          // 4096 rows

// Scratch (device globals; no allocation allowed)
__device__ float g_xhi[(size_t)Hv*BN];        // x transposed [c][row], tf32 hi
__device__ float g_xlo[(size_t)Hv*BN];        // x transposed [c][row], tf32 lo
__device__ float g_hhi[(size_t)BN*Hv];        // projected h [row][c], tf32 hi
__device__ float g_hlo[(size_t)BN*Hv];        // projected h [row][c], tf32 lo
__device__ float g_whi[Lv*Hv*Hv];             // gat_W tf32 hi (all layers)
__device__ float g_wlo[Lv*Hv*Hv];             // gat_W tf32 lo
__device__ float g_zbuf[Lv*2*BN + Bv*Hv];     // s1/s2 per layer + graph accum

#define GRAPH_OFF (Lv*2*BN)

// ---------------------------------------------------------------------------
// helpers
// ---------------------------------------------------------------------------
__device__ __forceinline__ void tf32split(float v, float& hi, float& lo) {
    uint32_t u;
    asm("cvt.rna.tf32.f32 %0, %1;" : "=r"(u) : "f"(v));
    hi = __uint_as_float(u);
    float r = v - hi;
    asm("cvt.rna.tf32.f32 %0, %1;" : "=r"(u) : "f"(r));
    lo = __uint_as_float(u);
}

// cp.async helpers
__device__ __forceinline__ void cp16(uint32_t s, const void* g) {
    asm volatile("cp.async.ca.shared.global [%0], [%1], 16;" :: "r"(s), "l"(g));
}
#define CP_COMMIT() asm volatile("cp.async.commit_group;")
#define CP_WAIT1()  asm volatile("cp.async.wait_group 1;")
#define CP_WAIT0()  asm volatile("cp.async.wait_group 0;")

// tf32 mma m16n8k8 (A row-major, B col-major, fp32 accum)
#define MMA_TF32(C, A, B0, B1)                                                 \
    asm("mma.sync.aligned.m16n8k8.row.col.f32.tf32.tf32.f32 "                  \
        "{%0,%1,%2,%3}, {%4,%5,%6,%7}, {%8,%9}, {%0,%1,%2,%3};"                \
        : "+f"((C)[0]), "+f"((C)[1]), "+f"((C)[2]), "+f"((C)[3])               \
        : "r"((A)[0]), "r"((A)[1]), "r"((A)[2]), "r"((A)[3]),                  \
          "r"(B0), "r"(B1))

// ---------------------------------------------------------------------------
// K0: split gat_W into tf32 hi/lo for all layers
// ---------------------------------------------------------------------------
__global__ void k_split_w(const float* __restrict__ gat_W)
{
    int idx = blockIdx.x*256 + threadIdx.x;
    float v = gat_W[idx];
    float hi, lo;
    tf32split(v, hi, lo);
    g_whi[idx] = hi;
    g_wlo[idx] = lo;
}

// ---------------------------------------------------------------------------
// K1: x = node_features @ W_node + b_node -> g_xhi/g_xlo (transposed, split)
// ---------------------------------------------------------------------------
#define NP_ROWS 8
__global__ void k_node_proj(const float* __restrict__ nf,
                            const float* __restrict__ W,
                            const float* __restrict__ bias)
{
    int row0 = blockIdx.x * NP_ROWS;
    int j    = threadIdx.x;

    __shared__ __align__(16) float sf[Fv * NP_ROWS];   // [f][r]
    __shared__ float st[NP_ROWS * 257];                // transpose tile

    for (int idx = j; idx < Fv*NP_ROWS; idx += 256) {
        int f = idx >> 3, r = idx & 7;
        sf[idx] = nf[(row0 + r)*Fv + f];
    }
    __syncthreads();

    float bj = bias[j];
    float acc[NP_ROWS];
#pragma unroll
    for (int r = 0; r < NP_ROWS; ++r) acc[r] = bj;

#pragma unroll 6
    for (int f = 0; f < Fv; ++f) {
        float w = W[f*Hv + j];
        const float4* xp = reinterpret_cast<const float4*>(&sf[f*NP_ROWS]);
        float4 xa = xp[0], xb = xp[1];
        acc[0] += xa.x * w;  acc[1] += xa.y * w;
        acc[2] += xa.z * w;  acc[3] += xa.w * w;
        acc[4] += xb.x * w;  acc[5] += xb.y * w;
        acc[6] += xb.z * w;  acc[7] += xb.w * w;
    }

#pragma unroll
    for (int r = 0; r < NP_ROWS; ++r)
        st[r*257 + j] = acc[r];
    __syncthreads();
    int r  = j & 7;
    int cb = j >> 3;          // 0..31
#pragma unroll
    for (int p = 0; p < 8; ++p) {
        int c = cb + 32*p;
        float v = st[r*257 + c];
        float hi, lo;
        tf32split(v, hi, lo);
        g_xhi[(size_t)c*BN + row0 + r] = hi;
        g_xlo[(size_t)c*BN + row0 + r] = lo;
    }
}

// ---------------------------------------------------------------------------
// K2: h = x @ gat_W[l] via tf32 mma.sync (3-pass split) + partial scores.
// 128 threads = 4 warps; block tile 32 rows x 32 cols; warp tile 16x16.
// grid = (BN/32, Hv/32) = 1024 blocks.
// ---------------------------------------------------------------------------
#define XSTR 40            // tile row stride (32 + 8 pad)
__global__ void __launch_bounds__(128)
k_gat_proj(const float* __restrict__ a,   // [512] (a1 | a2)
           int layer)
{
    const int row0 = blockIdx.x * 32;
    const int c0   = blockIdx.y * 32;
    const int t    = threadIdx.x;
    const int w    = t >> 5, lane = t & 31;
    const int g    = lane >> 2, tid = lane & 3;
    const int row0w = (w & 1) * 16;
    const int col0w = (w >> 1) * 16;

    const float* xhi = g_xhi;
    const float* xlo = g_xlo;
    const float* whi = g_whi + (size_t)layer*Hv*Hv;
    const float* wlo = g_wlo + (size_t)layer*Hv*Hv;
    float* s1 = g_zbuf + layer*2*BN;
    float* s2 = s1 + BN;

    __shared__ __align__(16) float sx[2][2][16*XSTR];  // [buf][hi/lo][k][row]
    __shared__ __align__(16) float sw[2][2][16*XSTR];  // [buf][hi/lo][k][col]
    const uint32_t sxa = (uint32_t)__cvta_generic_to_shared(sx);
    const uint32_t swa = (uint32_t)__cvta_generic_to_shared(sw);

    // staging: per array 16k x 8 float4-pieces = 128 = 1 per thread
#define PISSUE(kc, buf)                                                        \
    {                                                                          \
        _Pragma("unroll")                                                      \
        for (int m = 0; m < 2; ++m) {                                          \
            int k = t >> 3, f = t & 7;                                         \
            uint32_t doff = (((buf)*2 + m)*(16*XSTR) + k*XSTR + f*4)*4;        \
            const float* sxg = m ? &xlo[(size_t)((kc)+k)*BN + row0 + f*4]      \
                                 : &xhi[(size_t)((kc)+k)*BN + row0 + f*4];     \
            cp16(sxa + doff, sxg);                                             \
            const float* swg = m ? &wlo[((kc)+k)*Hv + c0 + f*4]                \
                                 : &whi[((kc)+k)*Hv + c0 + f*4];               \
            cp16(swa + doff, swg);                                             \
        }                                                                      \
        CP_COMMIT();                                                           \
    }

    float cacc[2][4];
#pragma unroll
    for (int nt = 0; nt < 2; ++nt)
#pragma unroll
        for (int q = 0; q < 4; ++q) cacc[nt][q] = 0.f;

    PISSUE(0, 0);

    const int NCH = Hv / 16;       // 16 chunks
#pragma unroll 4
    for (int c = 0; c < NCH; ++c) {
        const int cur = c & 1;
        if (c + 1 < NCH) {
            PISSUE((c+1)*16, (c+1)&1);
            CP_WAIT1();
        } else {
            CP_WAIT0();
        }
        __syncthreads();

        const float* sxh = sx[cur][0];
        const float* sxl = sx[cur][1];
        const float* swh = sw[cur][0];
        const float* swl = sw[cur][1];

#pragma unroll
        for (int ks = 0; ks < 16; ks += 8) {
            uint32_t ah[4], al[4];
            int rb = row0w + g;
            ah[0] = __float_as_uint(sxh[(ks+tid)*XSTR + rb]);
            ah[1] = __float_as_uint(sxh[(ks+tid)*XSTR + rb + 8]);
            ah[2] = __float_as_uint(sxh[(ks+tid+4)*XSTR + rb]);
            ah[3] = __float_as_uint(sxh[(ks+tid+4)*XSTR + rb + 8]);
            al[0] = __float_as_uint(sxl[(ks+tid)*XSTR + rb]);
            al[1] = __float_as_uint(sxl[(ks+tid)*XSTR + rb + 8]);
            al[2] = __float_as_uint(sxl[(ks+tid+4)*XSTR + rb]);
            al[3] = __float_as_uint(sxl[(ks+tid+4)*XSTR + rb + 8]);
#pragma unroll
            for (int nt = 0; nt < 2; ++nt) {
                int cb = col0w + nt*8 + g;
                uint32_t bh0 = __float_as_uint(swh[(ks+tid)*XSTR + cb]);
                uint32_t bh1 = __float_as_uint(swh[(ks+tid+4)*XSTR + cb]);
                uint32_t bl0 = __float_as_uint(swl[(ks+tid)*XSTR + cb]);
                uint32_t bl1 = __float_as_uint(swl[(ks+tid+4)*XSTR + cb]);
                MMA_TF32(cacc[nt], ah, bh0, bh1);   // hi*hi
                MMA_TF32(cacc[nt], ah, bl0, bl1);   // hi*lo
                MMA_TF32(cacc[nt], al, bh0, bh1);   // lo*hi
            }
        }
        __syncthreads();
    }
#undef PISSUE

    // epilogue: store h split, partial scores via quad-reduce + atomics
    float2 a1v[2], a2v[2];
#pragma unroll
    for (int nt = 0; nt < 2; ++nt) {
        a1v[nt] = *reinterpret_cast<const float2*>(&a[c0 + col0w + nt*8 + 2*tid]);
        a2v[nt] = *reinterpret_cast<const float2*>(&a[Hv + c0 + col0w + nt*8 + 2*tid]);
    }

    int rA = row0 + row0w + g;
    int rB = rA + 8;
    float p1A = 0.f, p2A = 0.f, p1B = 0.f, p2B = 0.f;
#pragma unroll
    for (int nt = 0; nt < 2; ++nt) {
        float c0v = cacc[nt][0], c1v = cacc[nt][1];
        float c2v = cacc[nt][2], c3v = cacc[nt][3];
        int colb = c0 + col0w + nt*8 + 2*tid;
        float h0h, h0l, h1h, h1l, h2h, h2l, h3h, h3l;
        tf32split(c0v, h0h, h0l);  tf32split(c1v, h1h, h1l);
        tf32split(c2v, h2h, h2l);  tf32split(c3v, h3h, h3l);
        *reinterpret_cast<float2*>(&g_hhi[(size_t)rA*Hv + colb]) = make_float2(h0h, h1h);
        *reinterpret_cast<float2*>(&g_hlo[(size_t)rA*Hv + colb]) = make_float2(h0l, h1l);
        *reinterpret_cast<float2*>(&g_hhi[(size_t)rB*Hv + colb]) = make_float2(h2h, h3h);
        *reinterpret_cast<float2*>(&g_hlo[(size_t)rB*Hv + colb]) = make_float2(h2l, h3l);
        p1A += c0v*a1v[nt].x + c1v*a1v[nt].y;
        p2A += c0v*a2v[nt].x + c1v*a2v[nt].y;
        p1B += c2v*a1v[nt].x + c3v*a1v[nt].y;
        p2B += c2v*a2v[nt].x + c3v*a2v[nt].y;
    }
#pragma unroll
    for (int off = 1; off <= 2; off <<= 1) {
        p1A += __shfl_xor_sync(0xffffffffu, p1A, off);
        p2A += __shfl_xor_sync(0xffffffffu, p2A, off);
        p1B += __shfl_xor_sync(0xffffffffu, p1B, off);
        p2B += __shfl_xor_sync(0xffffffffu, p2B, off);
    }
    if (tid == 0) {
        atomicAdd(&s1[rA], p1A);  atomicAdd(&s2[rA], p2A);
        atomicAdd(&s1[rB], p1B);  atomicAdd(&s2[rB], p2B);
    }
}

// ---------------------------------------------------------------------------
// K3: softmax + aggregation via tf32 mma.sync (3-pass, att split at load).
// 128 threads = 4 warps (all share rows); block tile 16 i x 64 c;
// warp tile 16x16. grid = (Nv/16, Hv/64, Bv) = 1024 blocks. smem ~31 KB.
// ---------------------------------------------------------------------------
#define SATT 24            // att [j][i_local(16)+pad] — conflict-free fragments
#define HSTR 72            // h tile stride (64 + 8 pad)
__global__ void __launch_bounds__(128)
k_gat_agg(const int* __restrict__ adj, int layer, int last)
{
    const int b  = blockIdx.z;
    const int i0 = blockIdx.x * 16;
    const int c0 = blockIdx.y * 64;
    const int t  = threadIdx.x;
    const int w  = t >> 5, lane = t & 31;
    const int g  = lane >> 2, tid = lane & 3;
    const int col0w = w * 16;

    const float* s1 = g_zbuf + layer*2*BN;
    const float* s2 = s1 + BN;

    __shared__ __align__(16) float att[Nv*SATT];       // fp32 att [j][i_local]
    __shared__ __align__(16) float sh[2][2][16*HSTR];  // h chunks hi/lo
    __shared__ float s2_sh[Nv];
    const uint32_t sha = (uint32_t)__cvta_generic_to_shared(sh);

    const float* hhb = g_hhi + (size_t)b*Nv*Hv;
    const float* hlb = g_hlo + (size_t)b*Nv*Hv;

#define ISSUE_H(jc, buf)                                                       \
    {                                                                          \
        _Pragma("unroll")                                                      \
        for (int m = 0; m < 4; ++m) {                                          \
            const int arr = m >> 1;                                            \
            int sub = t + 128*(m & 1);                                         \
            int k = sub >> 4, f = sub & 15;                                    \
            uint32_t doff = sha + (((buf)*2 + arr)*(16*HSTR) + k*HSTR + f*4)*4; \
            const float* src = arr ? &hlb[(size_t)((jc)+k)*Hv + c0 + f*4]      \
                                   : &hhb[(size_t)((jc)+k)*Hv + c0 + f*4];     \
            cp16(doff, src);                                                   \
        }                                                                      \
        CP_COMMIT();                                                           \
    }

    ISSUE_H(0, 0);       // overlap with softmax

    s2_sh[t] = s2[b*Nv + t];
    __syncthreads();

    // softmax: 4 rows per warp (4 warps x 4 = 16 rows); j = lane + q*32
#pragma unroll
    for (int rr = 0; rr < 4; ++rr) {
        int il = w*4 + rr;
        int i  = i0 + il;
        float s1i = s1[b*Nv + i];
        const int* adj_row = adj + (size_t)(b*Nv + i)*Nv;
        float e[4];
        float mx = NEG_INF;
#pragma unroll
        for (int q = 0; q < 4; ++q) {
            int jj = lane + q*32;
            float v = s1i + s2_sh[jj];
            v = (v > 0.f) ? v : ALPHA * v;
            v = (adj_row[jj] > 0) ? v : NEG_INF;
            e[q] = v;
            mx = fmaxf(mx, v);
        }
#pragma unroll
        for (int off = 16; off > 0; off >>= 1)
            mx = fmaxf(mx, __shfl_xor_sync(0xffffffffu, mx, off));
        float sum = 0.f;
#pragma unroll
        for (int q = 0; q < 4; ++q) { e[q] = __expf(e[q] - mx); sum += e[q]; }
#pragma unroll
        for (int off = 16; off > 0; off >>= 1)
            sum += __shfl_xor_sync(0xffffffffu, sum, off);
        float inv = 1.f / sum;
#pragma unroll
        for (int q = 0; q < 4; ++q)
            att[(lane + q*32)*SATT + il] = e[q] * inv;
    }
    __syncthreads();

    float cacc[2][4];
#pragma unroll
    for (int nt = 0; nt < 2; ++nt)
#pragma unroll
        for (int q = 0; q < 4; ++q) cacc[nt][q] = 0.f;

    const int NJC = Nv / 16;       // 8 chunks
#pragma unroll 4
    for (int c = 0; c < NJC; ++c) {
        const int cur = c & 1;
        if (c + 1 < NJC) {
            ISSUE_H((c+1)*16, (c+1)&1);
            CP_WAIT1();
        } else {
            CP_WAIT0();
        }
        __syncthreads();

        const float* shh = sh[cur][0];
        const float* shl = sh[cur][1];

#pragma unroll
        for (int ks = 0; ks < 16; ks += 8) {
            int jb = c*16 + ks;
            float av[4];
            av[0] = att[(jb+tid)*SATT + g];
            av[1] = att[(jb+tid)*SATT + g + 8];
            av[2] = att[(jb+tid+4)*SATT + g];
            av[3] = att[(jb+tid+4)*SATT + g + 8];
            uint32_t ah[4], al[4];
#pragma unroll
            for (int q = 0; q < 4; ++q) {
                uint32_t u;
                asm("cvt.rna.tf32.f32 %0, %1;" : "=r"(u) : "f"(av[q]));
                ah[q] = u;
                al[q] = __float_as_uint(av[q] - __uint_as_float(u));
            }
#pragma unroll
            for (int nt = 0; nt < 2; ++nt) {
                int cb = col0w + nt*8 + g;
                uint32_t bh0 = __float_as_uint(shh[(ks+tid)*HSTR + cb]);
                uint32_t bh1 = __float_as_uint(shh[(ks+tid+4)*HSTR + cb]);
                uint32_t bl0 = __float_as_uint(shl[(ks+tid)*HSTR + cb]);
                uint32_t bl1 = __float_as_uint(shl[(ks+tid+4)*HSTR + cb]);
                MMA_TF32(cacc[nt], ah, bh0, bh1);   // hi*hi
                MMA_TF32(cacc[nt], ah, bl0, bl1);   // hi*lo
                MMA_TF32(cacc[nt], al, bh0, bh1);   // lo*hi
            }
        }
        __syncthreads();
    }
#undef ISSUE_H

    if (last) {
        // fused mean partials: reduce relu over the block's 16 rows per column
        float* graph = g_zbuf + GRAPH_OFF;
#pragma unroll
        for (int nt = 0; nt < 2; ++nt) {
#pragma unroll
            for (int q2 = 0; q2 < 2; ++q2) {
                float p = fmaxf(cacc[nt][q2], 0.f) + fmaxf(cacc[nt][q2+2], 0.f);
#pragma unroll
                for (int off = 4; off <= 16; off <<= 1)
                    p += __shfl_xor_sync(0xffffffffu, p, off);
                if (g == 0) {
                    int col = c0 + col0w + nt*8 + 2*tid + q2;
                    atomicAdd(&graph[b*Hv + col], p);
                }
            }
        }
    } else {
        // transpose relu through smem (reuse att region: st[i][c], stride 68)
        __syncthreads();
        float* st = att;
        int rowA = g;
        int rowB = g + 8;
#pragma unroll
        for (int nt = 0; nt < 2; ++nt) {
            int colb = col0w + nt*8 + 2*tid;
            st[rowA*68 + colb]     = fmaxf(cacc[nt][0], 0.f);
            st[rowA*68 + colb + 1] = fmaxf(cacc[nt][1], 0.f);
            st[rowB*68 + colb]     = fmaxf(cacc[nt][2], 0.f);
            st[rowB*68 + colb + 1] = fmaxf(cacc[nt][3], 0.f);
        }
        __syncthreads();
        // thread t: channel ch = t&63, half = t>>6 -> 8 rows each, split store
        int ch   = t & 63;
        int half = t >> 6;
        size_t base = (size_t)(c0 + ch)*BN + b*Nv + i0 + half*8;
#pragma unroll
        for (int q = 0; q < 2; ++q) {
            int i = half*8 + 4*q;
            float4 hiv, lov;
            tf32split(st[(i+0)*68 + ch], hiv.x, lov.x);
            tf32split(st[(i+1)*68 + ch], hiv.y, lov.y);
            tf32split(st[(i+2)*68 + ch], hiv.z, lov.z);
            tf32split(st[(i+3)*68 + ch], hiv.w, lov.w);
            *reinterpret_cast<float4*>(&g_xhi[base + 4*q]) = hiv;
            *reinterpret_cast<float4*>(&g_xlo[base + 4*q]) = lov;
        }
    }
}

// ---------------------------------------------------------------------------
// K5: fused head. One block per batch element.
// ---------------------------------------------------------------------------
__global__ void k_head(const float* __restrict__ scaffold,
                       const float* __restrict__ W_sc,
                       const float* __restrict__ b_sc,
                       const float* __restrict__ gp_w1,
                       const float* __restrict__ gp_b1,
                       const float* __restrict__ gp_w2,
                       const float* __restrict__ gp_b2,
                       const float* __restrict__ out_w1,
                       const float* __restrict__ out_b1,
                       const float* __restrict__ out_w2,
                       const float* __restrict__ out_b2,
                       float* __restrict__ out)
{
    int b = blockIdx.x, t = threadIdx.x;
    const float* graph = g_zbuf + GRAPH_OFF;
    __shared__ float scaf[Sv];
    __shared__ float grow[Hv];
    __shared__ float sc[Hv];
    __shared__ float g1[128], sp1[128];
    __shared__ float c[128];
    __shared__ float hdn[128];

    if (t < Sv) scaf[t] = scaffold[b*Sv + t];
    grow[t] = graph[b*Hv + t] * (1.0f/Nv);
    __syncthreads();

    {
        float acc = b_sc[t];
#pragma unroll
        for (int k = 0; k < Sv; ++k)
            acc += scaf[k] * W_sc[k*Hv + t];
        sc[t] = acc;
    }
    __syncthreads();

    {
        int col = t & 127;
        const float* src = (t < 128) ? grow : sc;
        float acc = gp_b1[col];
#pragma unroll 4
        for (int k = 0; k < Hv; ++k)
            acc += src[k] * gp_w1[k*128 + col];
        acc = fmaxf(acc, 0.f);
        if (t < 128) g1[col] = acc; else sp1[col] = acc;
    }
    __syncthreads();

    if (t < 128) {
        int col = t & 63;
        const float* src = (t < 64) ? g1 : sp1;
        float acc = gp_b2[col];
#pragma unroll 4
        for (int k = 0; k < 128; ++k)
            acc += src[k] * gp_w2[k*64 + col];
        c[t] = fmaxf(acc, 0.f);
    }
    __syncthreads();

    if (t < 128) {
        float acc = out_b1[t];
#pragma unroll 4
        for (int k = 0; k < 128; ++k)
            acc += c[k] * out_w1[k*128 + t];
        hdn[t] = fmaxf(acc, 0.f);
    }
    __syncthreads();

    if (t < Tv) {
        float acc = out_b2[t];
#pragma unroll 4
        for (int k = 0; k < 128; ++k)
            acc += hdn[k] * out_w2[k*Tv + t];
        out[b*Tv + t] = acc;
    }
}

// ---------------------------------------------------------------------------
extern "C" void kernel_launch(void* const* d_in, const int* in_sizes, int n_in,
                              void* d_out, int out_size)
{
    const float* node_features     = (const float*)d_in[0];
    // d_in[1] = edge_features — unused by the reference
    const int*   adj_matrix        = (const int*)  d_in[2];
    const float* scaffold_features = (const float*)d_in[3];
    const float* W_node            = (const float*)d_in[4];
    const float* b_node            = (const float*)d_in[5];
    const float* gat_W             = (const float*)d_in[6];
    const float* gat_a             = (const float*)d_in[7];
    const float* W_sc              = (const float*)d_in[8];
    const float* b_sc              = (const float*)d_in[9];
    const float* gp_w1             = (const float*)d_in[10];
    const float* gp_b1             = (const float*)d_in[11];
    const float* gp_w2             = (const float*)d_in[12];
    const float* gp_b2             = (const float*)d_in[13];
    const float* out_w1            = (const float*)d_in[14];
    const float* out_b1            = (const float*)d_in[15];
    const float* out_w2            = (const float*)d_in[16];
    const float* out_b2            = (const float*)d_in[17];
    float* out = (float*)d_out;

    void* zp = nullptr;
    cudaGetSymbolAddress(&zp, g_zbuf);
    cudaMemsetAsync(zp, 0, (Lv*2*BN + Bv*Hv)*sizeof(float));

    k_split_w<<<Lv*Hv*Hv/256, 256>>>(gat_W);
    k_node_proj<<<BN/NP_ROWS, 256>>>(node_features, W_node, b_node);

    for (int l = 0; l < Lv; ++l) {
        dim3 pg(BN/32, Hv/32);                 // 128 x 8 = 1024 blocks, 128 thr
        k_gat_proj<<<pg, 128>>>(gat_a + (size_t)l*2*Hv, l);
        dim3 ag(Nv/16, Hv/64, Bv);             // 8 x 4 x 32 = 1024 blocks, 128 thr
        k_gat_agg<<<ag, 128>>>(adj_matrix, l, l == Lv-1);
    }

    k_head<<<Bv, 256>>>(scaffold_features, W_sc, b_sc,
                        gp_w1, gp_b1, gp_w2, gp_b2,
                        out_w1, out_b1, out_w2, out_b2, out);
}

// round 15
// speedup vs baseline: 1.1275x; 1.1275x over previous
#include <cuda_runtime.h>
#include <cuda_bf16.h>
#include <cstdint>

// Problem constants
#define Bv   32
#define Nv   128
#define Fv   78
#define Hv   256
#define Sv   20
#define Tv   13
#define Lv   3
#define ALPHA 0.2f
#define NEG_INF -9000000000000000.0f

#define BN (Bv*Nv)          // 4096 rows

// Scratch (device globals; no allocation allowed)
__device__ float g_xhi[(size_t)Hv*BN];        // x transposed [c][row], tf32 hi
__device__ float g_xlo[(size_t)Hv*BN];        // x transposed [c][row], tf32 lo
__device__ float g_h[(size_t)BN*Hv];          // projected h, fp32 [row][c]
__device__ float g_whi[Lv*Hv*Hv];             // gat_W tf32 hi (all layers)
__device__ float g_wlo[Lv*Hv*Hv];             // gat_W tf32 lo
__device__ float g_zbuf[Lv*2*BN + Bv*Hv];     // s1/s2 per layer + graph accum

#define GRAPH_OFF (Lv*2*BN)

// ---------------------------------------------------------------------------
// helpers
// ---------------------------------------------------------------------------
typedef unsigned long long u64;

__device__ __forceinline__ void fma2(u64& d, u64 a, u64 b) {
    asm("fma.rn.f32x2 %0, %1, %2, %0;" : "+l"(d) : "l"(a), "l"(b));
}
__device__ __forceinline__ u64 add2(u64 a, u64 b) {
    u64 d;
    asm("add.rn.f32x2 %0, %1, %2;" : "=l"(d) : "l"(a), "l"(b));
    return d;
}
__device__ __forceinline__ u64 pack2(float lo, float hi) {
    u64 r;
    asm("mov.b64 %0, {%1, %2};" : "=l"(r) : "f"(lo), "f"(hi));
    return r;
}
__device__ __forceinline__ float2 unpack2(u64 p) {
    float lo, hi;
    asm("mov.b64 {%0, %1}, %2;" : "=f"(lo), "=f"(hi) : "l"(p));
    return make_float2(lo, hi);
}
__device__ __forceinline__ void tf32split(float v, float& hi, float& lo) {
    uint32_t u;
    asm("cvt.rna.tf32.f32 %0, %1;" : "=r"(u) : "f"(v));
    hi = __uint_as_float(u);
    float r = v - hi;
    asm("cvt.rna.tf32.f32 %0, %1;" : "=r"(u) : "f"(r));
    lo = __uint_as_float(u);
}

// cp.async helpers
__device__ __forceinline__ void cp16(uint32_t s, const void* g) {
    asm volatile("cp.async.ca.shared.global [%0], [%1], 16;" :: "r"(s), "l"(g));
}
#define CP_COMMIT() asm volatile("cp.async.commit_group;")
#define CP_WAIT1()  asm volatile("cp.async.wait_group 1;")
#define CP_WAIT0()  asm volatile("cp.async.wait_group 0;")

// tf32 mma m16n8k8 (A row-major, B col-major, fp32 accum)
#define MMA_TF32(C, A, B0, B1)                                                 \
    asm("mma.sync.aligned.m16n8k8.row.col.f32.tf32.tf32.f32 "                  \
        "{%0,%1,%2,%3}, {%4,%5,%6,%7}, {%8,%9}, {%0,%1,%2,%3};"                \
        : "+f"((C)[0]), "+f"((C)[1]), "+f"((C)[2]), "+f"((C)[3])               \
        : "r"((A)[0]), "r"((A)[1]), "r"((A)[2]), "r"((A)[3]),                  \
          "r"(B0), "r"(B1))

// ---------------------------------------------------------------------------
// K0: split gat_W into tf32 hi/lo for all layers
// ---------------------------------------------------------------------------
__global__ void k_split_w(const float* __restrict__ gat_W)
{
    int idx = blockIdx.x*256 + threadIdx.x;
    float v = gat_W[idx];
    float hi, lo;
    tf32split(v, hi, lo);
    g_whi[idx] = hi;
    g_wlo[idx] = lo;
}

// ---------------------------------------------------------------------------
// K1: x = node_features @ W_node + b_node -> g_xhi/g_xlo (transposed, split)
// ---------------------------------------------------------------------------
#define NP_ROWS 8
__global__ void k_node_proj(const float* __restrict__ nf,
                            const float* __restrict__ W,
                            const float* __restrict__ bias)
{
    int row0 = blockIdx.x * NP_ROWS;
    int j    = threadIdx.x;

    __shared__ __align__(16) float sf[Fv * NP_ROWS];   // [f][r]
    __shared__ float st[NP_ROWS * 257];                // transpose tile

    for (int idx = j; idx < Fv*NP_ROWS; idx += 256) {
        int f = idx >> 3, r = idx & 7;
        sf[idx] = nf[(row0 + r)*Fv + f];
    }
    __syncthreads();

    float bj = bias[j];
    float acc[NP_ROWS];
#pragma unroll
    for (int r = 0; r < NP_ROWS; ++r) acc[r] = bj;

#pragma unroll 6
    for (int f = 0; f < Fv; ++f) {
        float w = W[f*Hv + j];
        const float4* xp = reinterpret_cast<const float4*>(&sf[f*NP_ROWS]);
        float4 xa = xp[0], xb = xp[1];
        acc[0] += xa.x * w;  acc[1] += xa.y * w;
        acc[2] += xa.z * w;  acc[3] += xa.w * w;
        acc[4] += xb.x * w;  acc[5] += xb.y * w;
        acc[6] += xb.z * w;  acc[7] += xb.w * w;
    }

#pragma unroll
    for (int r = 0; r < NP_ROWS; ++r)
        st[r*257 + j] = acc[r];
    __syncthreads();
    int r  = j & 7;
    int cb = j >> 3;          // 0..31
#pragma unroll
    for (int p = 0; p < 8; ++p) {
        int c = cb + 32*p;
        float v = st[r*257 + c];
        float hi, lo;
        tf32split(v, hi, lo);
        g_xhi[(size_t)c*BN + row0 + r] = hi;
        g_xlo[(size_t)c*BN + row0 + r] = lo;
    }
}

// ---------------------------------------------------------------------------
// K2: h = x @ gat_W[l] via tf32 mma.sync (3-pass split) + partial scores.
// 128 threads = 4 warps; block tile 32 rows x 64 cols; warp tile 16x32.
// grid = (BN/32, Hv/64) = 512 blocks. Epilogue: plain fp32 h stores.
// ---------------------------------------------------------------------------
#define XSTR 40            // x tile row stride
#define WSTR 72            // w tile row stride
__global__ void __launch_bounds__(128)
k_gat_proj(const float* __restrict__ a,   // [512] (a1 | a2)
           int layer)
{
    const int row0 = blockIdx.x * 32;
    const int c0   = blockIdx.y * 64;
    const int t    = threadIdx.x;
    const int w    = t >> 5, lane = t & 31;
    const int g    = lane >> 2, tid = lane & 3;
    const int row0w = (w & 1) * 16;
    const int col0w = (w >> 1) * 32;

    const float* xhi = g_xhi;
    const float* xlo = g_xlo;
    const float* whi = g_whi + (size_t)layer*Hv*Hv;
    const float* wlo = g_wlo + (size_t)layer*Hv*Hv;
    float* s1 = g_zbuf + layer*2*BN;
    float* s2 = s1 + BN;

    __shared__ __align__(16) float sx[2][2][16*XSTR];  // [buf][hi/lo]
    __shared__ __align__(16) float sw[2][2][16*WSTR];
    const uint32_t sxa = (uint32_t)__cvta_generic_to_shared(sx);
    const uint32_t swa = (uint32_t)__cvta_generic_to_shared(sw);

#define PISSUE(kc, buf)                                                        \
    {                                                                          \
        _Pragma("unroll")                                                      \
        for (int m = 0; m < 2; ++m) {                                          \
            int k = t >> 3, f = t & 7;                                         \
            uint32_t doff = sxa + (((buf)*2 + m)*(16*XSTR) + k*XSTR + f*4)*4;  \
            const float* src = m ? &xlo[(size_t)((kc)+k)*BN + row0 + f*4]      \
                                 : &xhi[(size_t)((kc)+k)*BN + row0 + f*4];     \
            cp16(doff, src);                                                   \
        }                                                                      \
        _Pragma("unroll")                                                      \
        for (int m = 0; m < 4; ++m) {                                          \
            const int arr = m >> 1;                                            \
            int sub = t + 128*(m & 1);                                         \
            int k = sub >> 4, f = sub & 15;                                    \
            uint32_t doff = swa + (((buf)*2 + arr)*(16*WSTR) + k*WSTR + f*4)*4; \
            const float* src = arr ? &wlo[((kc)+k)*Hv + c0 + f*4]              \
                                   : &whi[((kc)+k)*Hv + c0 + f*4];             \
            cp16(doff, src);                                                   \
        }                                                                      \
        CP_COMMIT();                                                           \
    }

    float cacc[4][4];
#pragma unroll
    for (int nt = 0; nt < 4; ++nt)
#pragma unroll
        for (int q = 0; q < 4; ++q) cacc[nt][q] = 0.f;

    PISSUE(0, 0);

    const int NCH = Hv / 16;       // 16 chunks
#pragma unroll 4
    for (int c = 0; c < NCH; ++c) {
        const int cur = c & 1;
        if (c + 1 < NCH) {
            PISSUE((c+1)*16, (c+1)&1);
            CP_WAIT1();
        } else {
            CP_WAIT0();
        }
        __syncthreads();

        const float* sxh = sx[cur][0];
        const float* sxl = sx[cur][1];
        const float* swh = sw[cur][0];
        const float* swl = sw[cur][1];

#pragma unroll
        for (int ks = 0; ks < 16; ks += 8) {
            uint32_t ah[4], al[4];
            int rb = row0w + g;
            ah[0] = __float_as_uint(sxh[(ks+tid)*XSTR + rb]);
            ah[1] = __float_as_uint(sxh[(ks+tid)*XSTR + rb + 8]);
            ah[2] = __float_as_uint(sxh[(ks+tid+4)*XSTR + rb]);
            ah[3] = __float_as_uint(sxh[(ks+tid+4)*XSTR + rb + 8]);
            al[0] = __float_as_uint(sxl[(ks+tid)*XSTR + rb]);
            al[1] = __float_as_uint(sxl[(ks+tid)*XSTR + rb + 8]);
            al[2] = __float_as_uint(sxl[(ks+tid+4)*XSTR + rb]);
            al[3] = __float_as_uint(sxl[(ks+tid+4)*XSTR + rb + 8]);
#pragma unroll
            for (int nt = 0; nt < 4; ++nt) {
                int cb = col0w + nt*8 + g;
                uint32_t bh0 = __float_as_uint(swh[(ks+tid)*WSTR + cb]);
                uint32_t bh1 = __float_as_uint(swh[(ks+tid+4)*WSTR + cb]);
                uint32_t bl0 = __float_as_uint(swl[(ks+tid)*WSTR + cb]);
                uint32_t bl1 = __float_as_uint(swl[(ks+tid+4)*WSTR + cb]);
                MMA_TF32(cacc[nt], ah, bh0, bh1);   // hi*hi
                MMA_TF32(cacc[nt], ah, bl0, bl1);   // hi*lo
                MMA_TF32(cacc[nt], al, bh0, bh1);   // lo*hi
            }
        }
        __syncthreads();
    }
#undef PISSUE

    // epilogue: store h fp32, partial scores via quad-reduce + atomics
    float2 a1v[4], a2v[4];
#pragma unroll
    for (int nt = 0; nt < 4; ++nt) {
        a1v[nt] = *reinterpret_cast<const float2*>(&a[c0 + col0w + nt*8 + 2*tid]);
        a2v[nt] = *reinterpret_cast<const float2*>(&a[Hv + c0 + col0w + nt*8 + 2*tid]);
    }

    int rA = row0 + row0w + g;
    int rB = rA + 8;
    float p1A = 0.f, p2A = 0.f, p1B = 0.f, p2B = 0.f;
#pragma unroll
    for (int nt = 0; nt < 4; ++nt) {
        float c0v = cacc[nt][0], c1v = cacc[nt][1];
        float c2v = cacc[nt][2], c3v = cacc[nt][3];
        int colb = c0 + col0w + nt*8 + 2*tid;
        *reinterpret_cast<float2*>(&g_h[(size_t)rA*Hv + colb]) = make_float2(c0v, c1v);
        *reinterpret_cast<float2*>(&g_h[(size_t)rB*Hv + colb]) = make_float2(c2v, c3v);
        p1A += c0v*a1v[nt].x + c1v*a1v[nt].y;
        p2A += c0v*a2v[nt].x + c1v*a2v[nt].y;
        p1B += c2v*a1v[nt].x + c3v*a1v[nt].y;
        p2B += c2v*a2v[nt].x + c3v*a2v[nt].y;
    }
#pragma unroll
    for (int off = 1; off <= 2; off <<= 1) {
        p1A += __shfl_xor_sync(0xffffffffu, p1A, off);
        p2A += __shfl_xor_sync(0xffffffffu, p2A, off);
        p1B += __shfl_xor_sync(0xffffffffu, p1B, off);
        p2B += __shfl_xor_sync(0xffffffffu, p2B, off);
    }
    if (tid == 0) {
        atomicAdd(&s1[rA], p1A);  atomicAdd(&s2[rA], p2A);
        atomicAdd(&s1[rB], p1B);  atomicAdd(&s2[rB], p2B);
    }
}

// ---------------------------------------------------------------------------
// K3: softmax attention + aggregation (+ fused mean on last layer)
// 256 threads = 2 groups x 128; tile 64 att-rows x 64 channels;
// thread = 4 rows x 8 cols (f32x2); groups split each staged j-chunk.
// (R11's exact agg — the best measured variant.)
// ---------------------------------------------------------------------------
#define JCa 32
#define ATS 68
__global__ void __launch_bounds__(256)
k_gat_agg(const int* __restrict__ adj, int layer, int last)
{
    const int b  = blockIdx.z;
    const int i0 = blockIdx.x * 64;
    const int c0 = blockIdx.y * 64;
    const int t  = threadIdx.x;            // 0..255
    const int g  = t >> 7;                 // j-half group
    const int tl = t & 127;
    const int tx = tl & 7, ty = tl >> 3;
    const int lane = t & 31, warp = t >> 5;

    const float* s1 = g_zbuf + layer*2*BN;
    const float* s2 = s1 + BN;

    __shared__ __align__(16) float s2_sh[Nv];
    __shared__ __align__(16) float att[Nv * ATS];     // [j][i_local]; reused as st
    __shared__ __align__(16) float shb[2][JCa*64];    // h chunks; reused for reduction

    const uint32_t shba = (uint32_t)__cvta_generic_to_shared(shb);
    const float* hb = g_h + (size_t)b*Nv*Hv;

#define ISSUE_H(jc, buf)                                                       \
    {                                                                          \
        _Pragma("unroll")                                                      \
        for (int m = 0; m < 2; ++m) {                                          \
            int idx = t + 256*m;                                               \
            int k = idx >> 4, f = idx & 15;                                    \
            uint32_t off = ((buf)*2048 + k*64 + f*4)*4;                        \
            cp16(shba + off, &hb[(size_t)((jc)+k)*Hv + c0 + f*4]);             \
        }                                                                      \
        CP_COMMIT();                                                           \
    }

    ISSUE_H(0, 0);       // overlap with softmax

    if (t < Nv) s2_sh[t] = s2[b*Nv + t];
    __syncthreads();

    // softmax: 8 rows per warp (8 warps x 8 = 64 rows); int4 adj loads
#pragma unroll
    for (int rr = 0; rr < 8; ++rr) {
        int il = warp*8 + rr;
        int i  = i0 + il;
        float s1i = s1[b*Nv + i];
        const int* adj_row = adj + (size_t)(b*Nv + i)*Nv;
        int4   am  = *reinterpret_cast<const int4*>(&adj_row[lane*4]);
        float4 s2v = *reinterpret_cast<const float4*>(&s2_sh[lane*4]);
        float e[4];
        {
            float v0 = s1i + s2v.x, v1 = s1i + s2v.y;
            float v2 = s1i + s2v.z, v3 = s1i + s2v.w;
            v0 = (v0 > 0.f) ? v0 : ALPHA*v0;  v1 = (v1 > 0.f) ? v1 : ALPHA*v1;
            v2 = (v2 > 0.f) ? v2 : ALPHA*v2;  v3 = (v3 > 0.f) ? v3 : ALPHA*v3;
            e[0] = (am.x > 0) ? v0 : NEG_INF;
            e[1] = (am.y > 0) ? v1 : NEG_INF;
            e[2] = (am.z > 0) ? v2 : NEG_INF;
            e[3] = (am.w > 0) ? v3 : NEG_INF;
        }
        float mx = fmaxf(fmaxf(e[0], e[1]), fmaxf(e[2], e[3]));
#pragma unroll
        for (int off = 16; off > 0; off >>= 1)
            mx = fmaxf(mx, __shfl_xor_sync(0xffffffffu, mx, off));
        float sum = 0.f;
#pragma unroll
        for (int q = 0; q < 4; ++q) { e[q] = __expf(e[q] - mx); sum += e[q]; }
#pragma unroll
        for (int off = 16; off > 0; off >>= 1)
            sum += __shfl_xor_sync(0xffffffffu, sum, off);
        float inv = 1.f / sum;
#pragma unroll
        for (int q = 0; q < 4; ++q)
            att[(lane*4 + q)*ATS + il] = e[q] * inv;
    }

    u64 acc[4][4];
#pragma unroll
    for (int r = 0; r < 4; ++r)
#pragma unroll
        for (int p = 0; p < 4; ++p) acc[r][p] = pack2(0.f, 0.f);

    const int NJC = Nv / JCa;      // 4
#pragma unroll
    for (int c = 0; c < NJC; ++c) {
        const int cur = c & 1;
        if (c + 1 < NJC) {
            ISSUE_H((c+1)*JCa, (c+1)&1);
            CP_WAIT1();
        } else {
            CP_WAIT0();
        }
        __syncthreads();

#pragma unroll 8
        for (int kk = 0; kk < 16; ++kk) {
            int kc = g*16 + kk;           // index within chunk
            int j  = c*JCa + kc;          // global j
            float4 ia = *reinterpret_cast<const float4*>(&att[j*ATS + ty*4]);
            const u64* hp = reinterpret_cast<const u64*>(&shb[cur][kc*64 + tx*4]);
            const u64* hq = reinterpret_cast<const u64*>(&shb[cur][kc*64 + 32 + tx*4]);
            u64 h0 = hp[0], h1 = hp[1], h2 = hq[0], h3 = hq[1];
            u64 i0p = pack2(ia.x, ia.x);
            u64 i1p = pack2(ia.y, ia.y);
            u64 i2p = pack2(ia.z, ia.z);
            u64 i3p = pack2(ia.w, ia.w);
            fma2(acc[0][0], i0p, h0); fma2(acc[0][1], i0p, h1);
            fma2(acc[0][2], i0p, h2); fma2(acc[0][3], i0p, h3);
            fma2(acc[1][0], i1p, h0); fma2(acc[1][1], i1p, h1);
            fma2(acc[1][2], i1p, h2); fma2(acc[1][3], i1p, h3);
            fma2(acc[2][0], i2p, h0); fma2(acc[2][1], i2p, h1);
            fma2(acc[2][2], i2p, h2); fma2(acc[2][3], i2p, h3);
            fma2(acc[3][0], i3p, h0); fma2(acc[3][1], i3p, h1);
            fma2(acc[3][2], i3p, h2); fma2(acc[3][3], i3p, h3);
        }
        __syncthreads();
    }
#undef ISSUE_H

    // split-j reduction through smem (reuse shb: 2048 u64 = 16KB)
    u64* red = reinterpret_cast<u64*>(shb);
    if (g == 1) {
#pragma unroll
        for (int r = 0; r < 4; ++r)
#pragma unroll
            for (int p = 0; p < 4; ++p)
                red[(r*4 + p)*128 + tl] = acc[r][p];
    }
    __syncthreads();

    if (last) {
        if (g == 0) {
            float* graph = g_zbuf + GRAPH_OFF;
            float colsum[8];
#pragma unroll
            for (int q = 0; q < 8; ++q) colsum[q] = 0.f;
#pragma unroll
            for (int r = 0; r < 4; ++r) {
#pragma unroll
                for (int p = 0; p < 4; ++p)
                    acc[r][p] = add2(acc[r][p], red[(r*4 + p)*128 + tl]);
                float2 v0 = unpack2(acc[r][0]);
                float2 v1 = unpack2(acc[r][1]);
                float2 v2 = unpack2(acc[r][2]);
                float2 v3 = unpack2(acc[r][3]);
                colsum[0] += fmaxf(v0.x, 0.f); colsum[1] += fmaxf(v0.y, 0.f);
                colsum[2] += fmaxf(v1.x, 0.f); colsum[3] += fmaxf(v1.y, 0.f);
                colsum[4] += fmaxf(v2.x, 0.f); colsum[5] += fmaxf(v2.y, 0.f);
                colsum[6] += fmaxf(v3.x, 0.f); colsum[7] += fmaxf(v3.y, 0.f);
            }
#pragma unroll
            for (int q = 0; q < 8; ++q) {
                int col = (q < 4) ? (tx*4 + q) : (32 + tx*4 + q - 4);
                atomicAdd(&graph[b*Hv + c0 + col], colsum[q]);
            }
        }
    } else {
        // group 0 reduces + writes st[i][c] (att reuse); all 256 store split x
        float* st = att;
        if (g == 0) {
#pragma unroll
            for (int r = 0; r < 4; ++r) {
#pragma unroll
                for (int p = 0; p < 4; ++p)
                    acc[r][p] = add2(acc[r][p], red[(r*4 + p)*128 + tl]);
                int il = ty*4 + r;
                float2 v0 = unpack2(acc[r][0]);
                float2 v1 = unpack2(acc[r][1]);
                float2 v2 = unpack2(acc[r][2]);
                float2 v3 = unpack2(acc[r][3]);
                st[il*ATS + tx*4 + 0]      = fmaxf(v0.x, 0.f);
                st[il*ATS + tx*4 + 1]      = fmaxf(v0.y, 0.f);
                st[il*ATS + tx*4 + 2]      = fmaxf(v1.x, 0.f);
                st[il*ATS + tx*4 + 3]      = fmaxf(v1.y, 0.f);
                st[il*ATS + 32 + tx*4 + 0] = fmaxf(v2.x, 0.f);
                st[il*ATS + 32 + tx*4 + 1] = fmaxf(v2.y, 0.f);
                st[il*ATS + 32 + tx*4 + 2] = fmaxf(v3.x, 0.f);
                st[il*ATS + 32 + tx*4 + 3] = fmaxf(v3.y, 0.f);
            }
        }
        __syncthreads();
        // thread t: channel ch = t&63, quarter qt = t>>6 -> 16 rows each
        int ch = t & 63;
        int qt = t >> 6;
        size_t base = (size_t)(c0 + ch)*BN + b*Nv + i0 + qt*16;
#pragma unroll
        for (int q = 0; q < 4; ++q) {
            int i = qt*16 + 4*q;
            float4 hiv, lov;
            tf32split(st[(i+0)*ATS + ch], hiv.x, lov.x);
            tf32split(st[(i+1)*ATS + ch], hiv.y, lov.y);
            tf32split(st[(i+2)*ATS + ch], hiv.z, lov.z);
            tf32split(st[(i+3)*ATS + ch], hiv.w, lov.w);
            *reinterpret_cast<float4*>(&g_xhi[base + 4*q]) = hiv;
            *reinterpret_cast<float4*>(&g_xlo[base + 4*q]) = lov;
        }
    }
}

// ---------------------------------------------------------------------------
// K5: fused head. One block per batch element.
// ---------------------------------------------------------------------------
__global__ void k_head(const float* __restrict__ scaffold,
                       const float* __restrict__ W_sc,
                       const float* __restrict__ b_sc,
                       const float* __restrict__ gp_w1,
                       const float* __restrict__ gp_b1,
                       const float* __restrict__ gp_w2,
                       const float* __restrict__ gp_b2,
                       const float* __restrict__ out_w1,
                       const float* __restrict__ out_b1,
                       const float* __restrict__ out_w2,
                       const float* __restrict__ out_b2,
                       float* __restrict__ out)
{
    int b = blockIdx.x, t = threadIdx.x;
    const float* graph = g_zbuf + GRAPH_OFF;
    __shared__ float scaf[Sv];
    __shared__ float grow[Hv];
    __shared__ float sc[Hv];
    __shared__ float g1[128], sp1[128];
    __shared__ float c[128];
    __shared__ float hdn[128];

    if (t < Sv) scaf[t] = scaffold[b*Sv + t];
    grow[t] = graph[b*Hv + t] * (1.0f/Nv);
    __syncthreads();

    {
        float acc = b_sc[t];
#pragma unroll
        for (int k = 0; k < Sv; ++k)
            acc += scaf[k] * W_sc[k*Hv + t];
        sc[t] = acc;
    }
    __syncthreads();

    {
        int col = t & 127;
        const float* src = (t < 128) ? grow : sc;
        float acc = gp_b1[col];
#pragma unroll 8
        for (int k = 0; k < Hv; ++k)
            acc += src[k] * gp_w1[k*128 + col];
        acc = fmaxf(acc, 0.f);
        if (t < 128) g1[col] = acc; else sp1[col] = acc;
    }
    __syncthreads();

    if (t < 128) {
        int col = t & 63;
        const float* src = (t < 64) ? g1 : sp1;
        float acc = gp_b2[col];
#pragma unroll 8
        for (int k = 0; k < 128; ++k)
            acc += src[k] * gp_w2[k*64 + col];
        c[t] = fmaxf(acc, 0.f);
    }
    __syncthreads();

    if (t < 128) {
        float acc = out_b1[t];
#pragma unroll 8
        for (int k = 0; k < 128; ++k)
            acc += c[k] * out_w1[k*128 + t];
        hdn[t] = fmaxf(acc, 0.f);
    }
    __syncthreads();

    if (t < Tv) {
        float acc = out_b2[t];
#pragma unroll 8
        for (int k = 0; k < 128; ++k)
            acc += hdn[k] * out_w2[k*Tv + t];
        out[b*Tv + t] = acc;
    }
}

// ---------------------------------------------------------------------------
extern "C" void kernel_launch(void* const* d_in, const int* in_sizes, int n_in,
                              void* d_out, int out_size)
{
    const float* node_features     = (const float*)d_in[0];
    // d_in[1] = edge_features — unused by the reference
    const int*   adj_matrix        = (const int*)  d_in[2];
    const float* scaffold_features = (const float*)d_in[3];
    const float* W_node            = (const float*)d_in[4];
    const float* b_node            = (const float*)d_in[5];
    const float* gat_W             = (const float*)d_in[6];
    const float* gat_a             = (const float*)d_in[7];
    const float* W_sc              = (const float*)d_in[8];
    const float* b_sc              = (const float*)d_in[9];
    const float* gp_w1             = (const float*)d_in[10];
    const float* gp_b1             = (const float*)d_in[11];
    const float* gp_w2             = (const float*)d_in[12];
    const float* gp_b2             = (const float*)d_in[13];
    const float* out_w1            = (const float*)d_in[14];
    const float* out_b1            = (const float*)d_in[15];
    const float* out_w2            = (const float*)d_in[16];
    const float* out_b2            = (const float*)d_in[17];
    float* out = (float*)d_out;

    void* zp = nullptr;
    cudaGetSymbolAddress(&zp, g_zbuf);
    cudaMemsetAsync(zp, 0, (Lv*2*BN + Bv*Hv)*sizeof(float));

    k_split_w<<<Lv*Hv*Hv/256, 256>>>(gat_W);
    k_node_proj<<<BN/NP_ROWS, 256>>>(node_features, W_node, b_node);

    for (int l = 0; l < Lv; ++l) {
        dim3 pg(BN/32, Hv/64);                 // 128 x 4 = 512 blocks, 128 thr
        k_gat_proj<<<pg, 128>>>(gat_a + (size_t)l*2*Hv, l);
        dim3 ag(Nv/64, Hv/64, Bv);             // 2 x 4 x 32 = 256 blocks, 256 thr
        k_gat_agg<<<ag, 256>>>(adj_matrix, l, l == Lv-1);
    }

    k_head<<<Bv, 256>>>(scaffold_features, W_sc, b_sc,
                        gp_w1, gp_b1, gp_w2, gp_b2,
                        out_w1, out_b1, out_w2, out_b2, out);
}